// round 2
// baseline (speedup 1.0000x reference)
#include <cuda_runtime.h>
#include <cuda_bf16.h>

// Problem constants (fixed by the dataset problem)
#define B_ 4
#define H_ 16
#define S_ 1024
#define D_ 128
#define SCALE 0.08838834764831845f   // 1/sqrt(128)
#define NEG_INF_ (-1.0e9f)

#define TQ 64          // query rows per block
#define TK 128         // key cols per tile
#define THREADS 256    // 8 warps; warp w owns rows 8w..8w+7; lane owns 4 cols (tx+32j)
#define QP_STRIDE 129  // padded smem strides (conflict-free column reads)
#define KV_STRIDE 129

#define SMEM_FLOATS (TQ * QP_STRIDE + TK * KV_STRIDE + TQ + TQ)
#define SMEM_BYTES (SMEM_FLOATS * 4)

// Fast exp(x) via exp2 with degree-7 Taylor of e^t on t in [0, ln2).
// FFMA-only (no MUFU). Rel err ~1.3e-6. Handles very negative x (masked) by
// clamping the exponent to -126 (result ~1.2e-38 ~ 0).
__device__ __forceinline__ float fast_expf(float x) {
    float y = x * 1.4426950408889634f;      // x * log2(e)
    y = fmaxf(y, -126.0f);
    float fl = floorf(y);
    float f  = y - fl;                      // [0,1)
    float t  = f * 0.6931471805599453f;     // [0, ln2)
    float p  = 1.98412698e-4f;              // 1/7!
    p = fmaf(p, t, 1.38888889e-3f);         // 1/6!
    p = fmaf(p, t, 8.33333333e-3f);         // 1/5!
    p = fmaf(p, t, 4.16666667e-2f);         // 1/4!
    p = fmaf(p, t, 0.16666667f);            // 1/3!
    p = fmaf(p, t, 0.5f);
    p = fmaf(p, t, 1.0f);
    p = fmaf(p, t, 1.0f);                   // p in [1,2)
    return __int_as_float(__float_as_int(p) + (((int)fl) << 23));
}

__device__ __forceinline__ float warpReduceMax(float v) {
    #pragma unroll
    for (int o = 16; o > 0; o >>= 1) v = fmaxf(v, __shfl_xor_sync(0xffffffffu, v, o));
    return v;
}
__device__ __forceinline__ float warpReduceSum(float v) {
    #pragma unroll
    for (int o = 16; o > 0; o >>= 1) v += __shfl_xor_sync(0xffffffffu, v, o);
    return v;
}

extern "C" __global__ void __launch_bounds__(THREADS, 2)
sdpa_kernel(const float* __restrict__ qg,
            const float* __restrict__ kg,
            const float* __restrict__ vg,
            const int*   __restrict__ maskg,
            float* __restrict__ out_ctx,   // [B,H,S,D]
            float* __restrict__ out_attn)  // [B,H,S,S]
{
    extern __shared__ float smem[];
    float* Qs   = smem;                          // TQ x QP_STRIDE (phase1: Q, phase2: P)
    float* Ks   = smem + TQ * QP_STRIDE;         // TK x KV_STRIDE (phase1: K, phase2: V)
    float* sm_m = Ks + TK * KV_STRIDE;           // TQ
    float* sm_il= sm_m + TQ;                     // TQ (1/l)

    const int bh = blockIdx.x;                   // 0..63
    const int qt = blockIdx.y;                   // 0..15
    const int b  = bh / H_;
    const int q0 = qt * TQ;

    const float* qb = qg + (size_t)bh * S_ * D_;
    const float* kb = kg + (size_t)bh * S_ * D_;
    const float* vb = vg + (size_t)bh * S_ * D_;
    const int*   mb = maskg + (size_t)b * S_ * S_;
    float*       ab = out_attn + (size_t)bh * S_ * S_;
    float*       cb = out_ctx  + (size_t)bh * S_ * D_;

    const int tid = threadIdx.x;
    const int w   = tid >> 5;
    const int tx  = tid & 31;
    const int r0  = w * 8;                       // warp's first query row (local)

    // ---- load Q tile (64 x 128) via float4 ----
    for (int idx = tid; idx < TQ * (D_ / 4); idx += THREADS) {
        int row = idx >> 5, c4 = (idx & 31) << 2;   // D_/4 == 32
        float4 qv4 = *(const float4*)(qb + (size_t)(q0 + row) * D_ + c4);
        float* dst = Qs + row * QP_STRIDE + c4;
        dst[0] = qv4.x; dst[1] = qv4.y; dst[2] = qv4.z; dst[3] = qv4.w;
    }
    __syncthreads();

    // per-row online stats (replicated across the warp's lanes)
    float m_run[8], l_run[8];
    #pragma unroll
    for (int i = 0; i < 8; i++) { m_run[i] = -3.0e38f; l_run[i] = 0.0f; }

    // ================= phase 1: raw scores + row stats =================
    for (int kt = 0; kt < S_ / TK; kt++) {
        const int k0 = kt * TK;
        // load K tile (128 x 128) via float4
        for (int idx = tid; idx < TK * (D_ / 4); idx += THREADS) {
            int row = idx >> 5, c4 = (idx & 31) << 2;
            float4 kv4 = *(const float4*)(kb + (size_t)(k0 + row) * D_ + c4);
            float* dst = Ks + row * KV_STRIDE + c4;
            dst[0] = kv4.x; dst[1] = kv4.y; dst[2] = kv4.z; dst[3] = kv4.w;
        }
        __syncthreads();

        float acc[8][4];
        #pragma unroll
        for (int i = 0; i < 8; i++)
            #pragma unroll
            for (int j = 0; j < 4; j++) acc[i][j] = 0.0f;

        #pragma unroll 4
        for (int kk = 0; kk < D_; kk++) {
            float kv[4];
            #pragma unroll
            for (int j = 0; j < 4; j++) kv[j] = Ks[(tx + 32 * j) * KV_STRIDE + kk];
            #pragma unroll
            for (int i = 0; i < 8; i++) {
                float qv = Qs[(r0 + i) * QP_STRIDE + kk];
                #pragma unroll
                for (int j = 0; j < 4; j++) acc[i][j] = fmaf(qv, kv[j], acc[i][j]);
            }
        }

        // scale + mask + stats + spill raw scores to global (attn region as scratch)
        #pragma unroll
        for (int i = 0; i < 8; i++) {
            const int rg = q0 + r0 + i;
            float s[4];
            float lmax = -3.0e38f;
            #pragma unroll
            for (int j = 0; j < 4; j++) {
                const int cg = k0 + tx + 32 * j;
                float sv = acc[i][j] * SCALE;
                int mv = __ldg(mb + (size_t)rg * S_ + cg);
                sv = (mv == 0) ? NEG_INF_ : sv;
                s[j] = sv;
                lmax = fmaxf(lmax, sv);
            }
            float mt = warpReduceMax(lmax);
            float m_new = fmaxf(m_run[i], mt);
            float lsum = 0.0f;
            #pragma unroll
            for (int j = 0; j < 4; j++) {
                lsum += fast_expf(s[j] - m_new);
                __stcs(ab + (size_t)rg * S_ + (k0 + tx + 32 * j), s[j]);
            }
            lsum = warpReduceSum(lsum);
            l_run[i] = l_run[i] * fast_expf(m_run[i] - m_new) + lsum;
            m_run[i] = m_new;
        }
        __syncthreads();   // before K tile is overwritten
    }

    // publish final row stats
    if (tx == 0) {
        #pragma unroll
        for (int i = 0; i < 8; i++) {
            sm_m[r0 + i]  = m_run[i];
            sm_il[r0 + i] = 1.0f / l_run[i];
        }
    }
    __syncthreads();

    // ================= phase 2: normalize attn + context = P @ V =================
    float cacc[8][4];
    #pragma unroll
    for (int i = 0; i < 8; i++)
        #pragma unroll
        for (int j = 0; j < 4; j++) cacc[i][j] = 0.0f;

    for (int kt = 0; kt < S_ / TK; kt++) {
        const int k0 = kt * TK;
        // load V tile (128 x 128) via float4
        for (int idx = tid; idx < TK * (D_ / 4); idx += THREADS) {
            int row = idx >> 5, c4 = (idx & 31) << 2;
            float4 vv4 = *(const float4*)(vb + (size_t)(k0 + row) * D_ + c4);
            float* dst = Ks + row * KV_STRIDE + c4;
            dst[0] = vv4.x; dst[1] = vv4.y; dst[2] = vv4.z; dst[3] = vv4.w;
        }
        // load raw scores, normalize, write final attn, stage P tile in smem
        for (int idx = tid; idx < TQ * (TK / 4); idx += THREADS) {
            int row = idx >> 5, c4 = (idx & 31) << 2;   // TK/4 == 32
            float4 sv4 = *(const float4*)(ab + (size_t)(q0 + row) * S_ + (k0 + c4));
            float m  = sm_m[row], il = sm_il[row];
            float4 p4;
            p4.x = fast_expf(sv4.x - m) * il;
            p4.y = fast_expf(sv4.y - m) * il;
            p4.z = fast_expf(sv4.z - m) * il;
            p4.w = fast_expf(sv4.w - m) * il;
            __stcs((float4*)(ab + (size_t)(q0 + row) * S_ + (k0 + c4)), p4);
            float* dst = Qs + row * QP_STRIDE + c4;
            dst[0] = p4.x; dst[1] = p4.y; dst[2] = p4.z; dst[3] = p4.w;
        }
        __syncthreads();

        #pragma unroll 4
        for (int kk = 0; kk < TK; kk++) {
            float vv[4];
            #pragma unroll
            for (int j = 0; j < 4; j++) vv[j] = Ks[kk * KV_STRIDE + tx + 32 * j];
            #pragma unroll
            for (int i = 0; i < 8; i++) {
                float pv = Qs[(r0 + i) * QP_STRIDE + kk];
                #pragma unroll
                for (int j = 0; j < 4; j++) cacc[i][j] = fmaf(pv, vv[j], cacc[i][j]);
            }
        }
        __syncthreads();
    }

    // store context
    #pragma unroll
    for (int i = 0; i < 8; i++) {
        const int rg = q0 + r0 + i;
        #pragma unroll
        for (int j = 0; j < 4; j++)
            cb[(size_t)rg * D_ + tx + 32 * j] = cacc[i][j];
    }
}

extern "C" void kernel_launch(void* const* d_in, const int* in_sizes, int n_in,
                              void* d_out, int out_size) {
    const float* q    = (const float*)d_in[0];
    const float* k    = (const float*)d_in[1];
    const float* v    = (const float*)d_in[2];
    const int*   mask = (const int*)d_in[3];

    float* out_ctx  = (float*)d_out;
    float* out_attn = out_ctx + (size_t)B_ * H_ * S_ * D_;   // context first, then attn

    static int attr_set = 0;
    if (!attr_set) {
        cudaFuncSetAttribute(sdpa_kernel, cudaFuncAttributeMaxDynamicSharedMemorySize, SMEM_BYTES);
        attr_set = 1;
    }

    dim3 grid(B_ * H_, S_ / TQ);
    sdpa_kernel<<<grid, THREADS, SMEM_BYTES>>>(q, k, v, mask, out_ctx, out_attn);
}

// round 6
// speedup vs baseline: 1.0958x; 1.0958x over previous
#include <cuda_runtime.h>
#include <cuda_bf16.h>
#include <cstdint>

// ---------------- problem constants ----------------
#define B_ 4
#define H_ 16
#define S_ 1024
#define D_ 128
#define BH_ 64
#define SCALE 0.08838834764831845f   // 1/sqrt(128)
#define NEG_INF_ (-1.0e9f)

#define TQ 128            // query rows per block (M)
#define TK 128            // key rows per tile (N)
#define THREADS 256       // 8 warps: 4 m-warps x 2 n-warps, warp tile 32x64

// ---------------- device scratch (bf16 hi/lo splits) ----------------
#define NELEM (BH_ * S_ * D_)   // 8,388,608
__device__ __nv_bfloat16 g_qhi[NELEM];
__device__ __nv_bfloat16 g_qlo[NELEM];
__device__ __nv_bfloat16 g_khi[NELEM];
__device__ __nv_bfloat16 g_klo[NELEM];
__device__ __nv_bfloat16 g_vthi[NELEM];  // V^T: [bh, d, s]
__device__ __nv_bfloat16 g_vtlo[NELEM];

// ---------------- smem layout (bytes) ----------------
#define SM_RED   0        // float[128]
#define SM_MNEW  512      // float[128]
#define SM_MRUN  1024     // float[128]
#define SM_LRUN  1536     // float[128]
#define SM_IL    2048     // float[128]
#define SM_QHI   3072     // 128x128 bf16 swizzled tile (32KB); phase2: P hi
#define SM_QLO   (SM_QHI + 32768)
#define SM_KHI   (SM_QLO + 32768)  // phase1: K, phase2: V^T
#define SM_KLO   (SM_KHI + 32768)
#define SMEM_MAIN (SM_KLO + 32768) // 134144 bytes

// Swizzled tile addressing: 128 rows x 256B; 16B chunk j stored at j ^ (r&7).
__device__ __forceinline__ uint32_t swz16(int r, int cb) {   // cb multiple of 16
    return (uint32_t)(r * 256 + ((((cb >> 4) ^ (r & 7)) << 4)));
}
__device__ __forceinline__ uint32_t swzb(int r, int cb) {    // any byte offset
    return (uint32_t)(r * 256 + ((((cb >> 4) ^ (r & 7)) << 4) | (cb & 15)));
}

__device__ __forceinline__ uint32_t smem_u32(const void* p) {
    uint32_t a;
    asm("{ .reg .u64 t; cvta.to.shared.u64 t, %1; cvt.u32.u64 %0, t; }" : "=r"(a) : "l"(p));
    return a;
}
__device__ __forceinline__ void ldsm4(uint32_t* r, uint32_t addr) {
    asm volatile("ldmatrix.sync.aligned.m8n8.x4.shared.b16 {%0,%1,%2,%3}, [%4];"
                 : "=r"(r[0]), "=r"(r[1]), "=r"(r[2]), "=r"(r[3]) : "r"(addr));
}
__device__ __forceinline__ void mma16816(float* c, const uint32_t* a,
                                         uint32_t b0, uint32_t b1) {
    asm volatile(
        "mma.sync.aligned.m16n8k16.row.col.f32.bf16.bf16.f32 "
        "{%0,%1,%2,%3}, {%4,%5,%6,%7}, {%8,%9}, {%0,%1,%2,%3};"
        : "+f"(c[0]), "+f"(c[1]), "+f"(c[2]), "+f"(c[3])
        : "r"(a[0]), "r"(a[1]), "r"(a[2]), "r"(a[3]), "r"(b0), "r"(b1));
}

// Stage a 128x128 bf16 tile (row stride in elems) into the swizzled smem tile.
__device__ __forceinline__ void stage_tile(unsigned char* sm, uint32_t dst,
                                           const __nv_bfloat16* src, int stride, int tid) {
    for (int idx = tid; idx < 2048; idx += THREADS) {
        int r = idx >> 4, j = idx & 15;
        uint4 v = *(const uint4*)(src + (size_t)r * stride + j * 8);
        *(uint4*)(sm + dst + (uint32_t)(r * 256 + ((j ^ (r & 7)) << 4))) = v;
    }
}

// One 128x128x128 GEMM tile (3-pass split), warp tile 32x64, acc += A@B^T.
__device__ __forceinline__ void warp_gemm_tile(float acc[2][8][4], uint32_t smb,
                                               const uint32_t* aoff, const uint32_t* boff,
                                               int wm, int wn, int lane) {
    const int arow = wm * 32 + (lane & 15);
    const int brow = wn * 64 + (lane & 15);
    const int chalf = (lane >> 4) * 16;    // byte offset of column half
    #pragma unroll
    for (int p = 0; p < 3; p++) {
        const uint32_t Ab = smb + aoff[p];
        const uint32_t Bb = smb + boff[p];
        #pragma unroll
        for (int ks = 0; ks < 8; ks++) {
            const int cb = ks * 32 + chalf;
            uint32_t a[2][4];
            #pragma unroll
            for (int mi = 0; mi < 2; mi++)
                ldsm4(a[mi], Ab + swz16(arow + mi * 16, cb));
            uint32_t b[4][4];
            #pragma unroll
            for (int nj = 0; nj < 4; nj++)
                ldsm4(b[nj], Bb + swz16(brow + nj * 16, cb));
            #pragma unroll
            for (int mi = 0; mi < 2; mi++)
                #pragma unroll
                for (int nj = 0; nj < 4; nj++) {
                    mma16816(acc[mi][2 * nj],     a[mi], b[nj][0], b[nj][2]);
                    mma16816(acc[mi][2 * nj + 1], a[mi], b[nj][1], b[nj][3]);
                }
        }
    }
}

// FFMA-only exp (no MUFU). rel err ~1.3e-6; clamps for very negative x.
__device__ __forceinline__ float fast_expf(float x) {
    float y = x * 1.4426950408889634f;
    y = fmaxf(y, -126.0f);
    float fl = floorf(y);
    float t  = (y - fl) * 0.6931471805599453f;
    float p  = 1.98412698e-4f;
    p = fmaf(p, t, 1.38888889e-3f);
    p = fmaf(p, t, 8.33333333e-3f);
    p = fmaf(p, t, 4.16666667e-2f);
    p = fmaf(p, t, 0.16666667f);
    p = fmaf(p, t, 0.5f);
    p = fmaf(p, t, 1.0f);
    p = fmaf(p, t, 1.0f);
    return __int_as_float(__float_as_int(p) + (((int)fl) << 23));
}

__device__ __forceinline__ void split_bf16(float x, __nv_bfloat16& h, __nv_bfloat16& l) {
    h = __float2bfloat16(x);
    l = __float2bfloat16(x - __bfloat162float(h));
}

// ---------------- pre-kernels: fp32 -> bf16 hi/lo (write device globals directly;
// no cudaGetSymbolAddress in the capture path) ----------------
__global__ void convert_split_q_kernel(const float* __restrict__ src, int n4) {
    int i = blockIdx.x * blockDim.x + threadIdx.x;
    if (i >= n4) return;
    float4 v = ((const float4*)src)[i];
    __nv_bfloat16 h0, l0, h1, l1, h2, l2, h3, l3;
    split_bf16(v.x, h0, l0); split_bf16(v.y, h1, l1);
    split_bf16(v.z, h2, l2); split_bf16(v.w, h3, l3);
    ((ushort4*)g_qhi)[i] = make_ushort4(__bfloat16_as_ushort(h0), __bfloat16_as_ushort(h1),
                                        __bfloat16_as_ushort(h2), __bfloat16_as_ushort(h3));
    ((ushort4*)g_qlo)[i] = make_ushort4(__bfloat16_as_ushort(l0), __bfloat16_as_ushort(l1),
                                        __bfloat16_as_ushort(l2), __bfloat16_as_ushort(l3));
}
__global__ void convert_split_k_kernel(const float* __restrict__ src, int n4) {
    int i = blockIdx.x * blockDim.x + threadIdx.x;
    if (i >= n4) return;
    float4 v = ((const float4*)src)[i];
    __nv_bfloat16 h0, l0, h1, l1, h2, l2, h3, l3;
    split_bf16(v.x, h0, l0); split_bf16(v.y, h1, l1);
    split_bf16(v.z, h2, l2); split_bf16(v.w, h3, l3);
    ((ushort4*)g_khi)[i] = make_ushort4(__bfloat16_as_ushort(h0), __bfloat16_as_ushort(h1),
                                        __bfloat16_as_ushort(h2), __bfloat16_as_ushort(h3));
    ((ushort4*)g_klo)[i] = make_ushort4(__bfloat16_as_ushort(l0), __bfloat16_as_ushort(l1),
                                        __bfloat16_as_ushort(l2), __bfloat16_as_ushort(l3));
}

// ---------------- pre-kernel: V -> V^T (bf16 hi/lo) ----------------
#define TP_PAD 136
__global__ void transpose_v_kernel(const float* __restrict__ v) {
    extern __shared__ __align__(16) unsigned char tsm[];
    __nv_bfloat16* sh = (__nv_bfloat16*)tsm;                  // [128][136]
    __nv_bfloat16* sl = sh + 128 * TP_PAD;
    const int bh = blockIdx.x;
    const int s0 = blockIdx.y * 128;
    const int tid = threadIdx.x;

    for (int idx = tid; idx < 128 * 32; idx += THREADS) {
        int row = idx >> 5;
        int c4  = (idx & 31) << 2;
        float4 vv = *(const float4*)(v + ((size_t)(bh * S_ + s0 + row)) * D_ + c4);
        float vals[4] = {vv.x, vv.y, vv.z, vv.w};
        #pragma unroll
        for (int i = 0; i < 4; i++) {
            __nv_bfloat16 h, l;
            split_bf16(vals[i], h, l);
            sh[(c4 + i) * TP_PAD + row] = h;
            sl[(c4 + i) * TP_PAD + row] = l;
        }
    }
    __syncthreads();
    for (int idx = tid; idx < 128 * 16; idx += THREADS) {
        int d  = idx >> 4;
        int c8 = (idx & 15) << 3;
        uint4 hv = *(const uint4*)(sh + d * TP_PAD + c8);
        uint4 lv = *(const uint4*)(sl + d * TP_PAD + c8);
        size_t go = ((size_t)bh * D_ + d) * S_ + s0 + c8;
        *(uint4*)(g_vthi + go) = hv;
        *(uint4*)(g_vtlo + go) = lv;
    }
}

// ---------------- main attention kernel ----------------
__global__ void __launch_bounds__(THREADS)
sdpa_mma_kernel(const int* __restrict__ maskg,
                float* __restrict__ out_ctx,
                float* __restrict__ out_attn) {
    extern __shared__ __align__(256) unsigned char sm[];
    const uint32_t smb = smem_u32(sm);

    const int bh = blockIdx.x;
    const int q0 = blockIdx.y * TQ;
    const int b  = bh / H_;
    const int tid  = threadIdx.x;
    const int w    = tid >> 5;
    const int lane = tid & 31;
    const int wm = w >> 1;          // 0..3
    const int wn = w & 1;           // 0..1
    const int lr = lane >> 2;       // 0..7
    const int lc = lane & 3;        // 0..3

    const int*   mb  = maskg   + (size_t)b  * S_ * S_;
    float*       ab  = out_attn + (size_t)bh * S_ * S_;
    float*       cbp = out_ctx  + (size_t)bh * S_ * D_;

    float* RED  = (float*)(sm + SM_RED);
    float* MNEW = (float*)(sm + SM_MNEW);
    float* MRUN = (float*)(sm + SM_MRUN);
    float* LRUN = (float*)(sm + SM_LRUN);
    float* SIL  = (float*)(sm + SM_IL);

    // local row index for quadrant q = 2*mi + p  (p: +8 row within m16)
    int rowq[4];
    #pragma unroll
    for (int qq = 0; qq < 4; qq++)
        rowq[qq] = wm * 32 + ((qq >> 1) << 4) + ((qq & 1) << 3) + lr;

    if (tid < 128) { MRUN[tid] = -3.0e38f; LRUN[tid] = 0.0f; }

    // stage Q hi/lo (persistent through phase 1)
    stage_tile(sm, SM_QHI, g_qhi + ((size_t)bh * S_ + q0) * D_, D_, tid);
    stage_tile(sm, SM_QLO, g_qlo + ((size_t)bh * S_ + q0) * D_, D_, tid);

    const uint32_t aoff[3] = {SM_QHI, SM_QHI, SM_QLO};
    const uint32_t boff[3] = {SM_KHI, SM_KLO, SM_KHI};

    // ================= phase 1: S = scale*Q@K^T, masked; row stats; raw spill ====
    for (int kt = 0; kt < S_ / TK; kt++) {
        const int k0 = kt * TK;
        __syncthreads();   // prev tile fully consumed (incl. RED)
        stage_tile(sm, SM_KHI, g_khi + ((size_t)bh * S_ + k0) * D_, D_, tid);
        stage_tile(sm, SM_KLO, g_klo + ((size_t)bh * S_ + k0) * D_, D_, tid);
        __syncthreads();

        float acc[2][8][4];
        #pragma unroll
        for (int mi = 0; mi < 2; mi++)
            #pragma unroll
            for (int ni = 0; ni < 8; ni++)
                #pragma unroll
                for (int e = 0; e < 4; e++) acc[mi][ni][e] = 0.0f;

        warp_gemm_tile(acc, smb, aoff, boff, wm, wn, lane);

        // ---- epilogue: scale + mask (in place), row max ----
        float pmax[4] = {-3.0e38f, -3.0e38f, -3.0e38f, -3.0e38f};
        #pragma unroll
        for (int mi = 0; mi < 2; mi++) {
            #pragma unroll
            for (int ni = 0; ni < 8; ni++) {
                const int cg = k0 + wn * 64 + ni * 8 + lc * 2;
                const int rg0 = q0 + rowq[2 * mi];
                const int rg1 = q0 + rowq[2 * mi + 1];
                int2 m0 = __ldg((const int2*)(mb + (size_t)rg0 * S_ + cg));
                int2 m1 = __ldg((const int2*)(mb + (size_t)rg1 * S_ + cg));
                float* c = acc[mi][ni];
                c[0] = (m0.x == 0) ? NEG_INF_ : c[0] * SCALE;
                c[1] = (m0.y == 0) ? NEG_INF_ : c[1] * SCALE;
                c[2] = (m1.x == 0) ? NEG_INF_ : c[2] * SCALE;
                c[3] = (m1.y == 0) ? NEG_INF_ : c[3] * SCALE;
                pmax[2 * mi]     = fmaxf(pmax[2 * mi],     fmaxf(c[0], c[1]));
                pmax[2 * mi + 1] = fmaxf(pmax[2 * mi + 1], fmaxf(c[2], c[3]));
            }
        }
        #pragma unroll
        for (int qq = 0; qq < 4; qq++) {
            pmax[qq] = fmaxf(pmax[qq], __shfl_xor_sync(0xffffffffu, pmax[qq], 1));
            pmax[qq] = fmaxf(pmax[qq], __shfl_xor_sync(0xffffffffu, pmax[qq], 2));
        }
        if (wn == 1) RED[rowq[lc]] = pmax[lc];
        __syncthreads();
        if (wn == 0) {
            const int row = rowq[lc];
            MNEW[row] = fmaxf(MRUN[row], fmaxf(pmax[lc], RED[row]));
        }
        __syncthreads();

        float mnew[4];
        #pragma unroll
        for (int qq = 0; qq < 4; qq++) mnew[qq] = MNEW[rowq[qq]];

        // ---- exp partial sums + raw spill ----
        float psum[4] = {0.0f, 0.0f, 0.0f, 0.0f};
        #pragma unroll
        for (int mi = 0; mi < 2; mi++) {
            #pragma unroll
            for (int ni = 0; ni < 8; ni++) {
                const int cg = k0 + wn * 64 + ni * 8 + lc * 2;
                float* c = acc[mi][ni];
                psum[2 * mi]     += fast_expf(c[0] - mnew[2 * mi]) + fast_expf(c[1] - mnew[2 * mi]);
                psum[2 * mi + 1] += fast_expf(c[2] - mnew[2 * mi + 1]) + fast_expf(c[3] - mnew[2 * mi + 1]);
                __stcs((float2*)(ab + (size_t)(q0 + rowq[2 * mi]) * S_ + cg),
                       make_float2(c[0], c[1]));
                __stcs((float2*)(ab + (size_t)(q0 + rowq[2 * mi + 1]) * S_ + cg),
                       make_float2(c[2], c[3]));
            }
        }
        #pragma unroll
        for (int qq = 0; qq < 4; qq++) {
            psum[qq] += __shfl_xor_sync(0xffffffffu, psum[qq], 1);
            psum[qq] += __shfl_xor_sync(0xffffffffu, psum[qq], 2);
        }
        if (wn == 1) RED[rowq[lc]] = psum[lc];
        __syncthreads();
        if (wn == 0) {
            const int row = rowq[lc];
            const float mn = MNEW[row];
            LRUN[row] = LRUN[row] * fast_expf(MRUN[row] - mn) + psum[lc] + RED[row];
            MRUN[row] = mn;
        }
    }

    __syncthreads();
    if (tid < 128) SIL[tid] = 1.0f / LRUN[tid];

    // ================= phase 2: attn = softmax; ctx = P @ V ======================
    float cacc[2][8][4];
    #pragma unroll
    for (int mi = 0; mi < 2; mi++)
        #pragma unroll
        for (int ni = 0; ni < 8; ni++)
            #pragma unroll
            for (int e = 0; e < 4; e++) cacc[mi][ni][e] = 0.0f;

    for (int kt = 0; kt < S_ / TK; kt++) {
        const int k0 = kt * TK;
        __syncthreads();
        stage_tile(sm, SM_KHI, g_vthi + (size_t)bh * D_ * S_ + k0, S_, tid);
        stage_tile(sm, SM_KLO, g_vtlo + (size_t)bh * D_ * S_ + k0, S_, tid);

        // normalize raw scores -> final attn + P hi/lo tiles in smem
        for (int idx = tid; idx < 128 * 32; idx += THREADS) {
            int row = idx >> 5;
            int c4  = (idx & 31) << 2;
            const int rg = q0 + row;
            float4 raw = __ldcs((const float4*)(ab + (size_t)rg * S_ + k0 + c4));
            float m  = MRUN[row], il = SIL[row];
            float4 p;
            p.x = fast_expf(raw.x - m) * il;
            p.y = fast_expf(raw.y - m) * il;
            p.z = fast_expf(raw.z - m) * il;
            p.w = fast_expf(raw.w - m) * il;
            __stcs((float4*)(ab + (size_t)rg * S_ + k0 + c4), p);
            __nv_bfloat16 h0,l0,h1,l1,h2,l2,h3,l3;
            split_bf16(p.x, h0, l0); split_bf16(p.y, h1, l1);
            split_bf16(p.z, h2, l2); split_bf16(p.w, h3, l3);
            ushort4 hv = make_ushort4(__bfloat16_as_ushort(h0), __bfloat16_as_ushort(h1),
                                      __bfloat16_as_ushort(h2), __bfloat16_as_ushort(h3));
            ushort4 lv = make_ushort4(__bfloat16_as_ushort(l0), __bfloat16_as_ushort(l1),
                                      __bfloat16_as_ushort(l2), __bfloat16_as_ushort(l3));
            uint32_t off = swzb(row, c4 * 2);
            *(ushort4*)(sm + SM_QHI + off) = hv;
            *(ushort4*)(sm + SM_QLO + off) = lv;
        }
        __syncthreads();

        warp_gemm_tile(cacc, smb, aoff, boff, wm, wn, lane);
    }

    // store context: cols cg = wn*64 + ni*8 + lc*2
    #pragma unroll
    for (int mi = 0; mi < 2; mi++) {
        #pragma unroll
        for (int ni = 0; ni < 8; ni++) {
            const int cg = wn * 64 + ni * 8 + lc * 2;
            float* c = cacc[mi][ni];
            *(float2*)(cbp + (size_t)(q0 + rowq[2 * mi]) * D_ + cg)     = make_float2(c[0], c[1]);
            *(float2*)(cbp + (size_t)(q0 + rowq[2 * mi + 1]) * D_ + cg) = make_float2(c[2], c[3]);
        }
    }
}

// ---------------- launch ----------------
extern "C" void kernel_launch(void* const* d_in, const int* in_sizes, int n_in,
                              void* d_out, int out_size) {
    const float* q    = (const float*)d_in[0];
    const float* k    = (const float*)d_in[1];
    const float* v    = (const float*)d_in[2];
    const int*   mask = (const int*)d_in[3];

    float* out_ctx  = (float*)d_out;
    float* out_attn = out_ctx + (size_t)BH_ * S_ * D_;

    static int attr_set = 0;
    if (!attr_set) {
        cudaFuncSetAttribute(sdpa_mma_kernel, cudaFuncAttributeMaxDynamicSharedMemorySize, SMEM_MAIN);
        cudaFuncSetAttribute(transpose_v_kernel, cudaFuncAttributeMaxDynamicSharedMemorySize,
                             2 * 128 * TP_PAD * 2);
        attr_set = 1;
    }

    const int n4 = NELEM / 4;
    convert_split_q_kernel<<<(n4 + 255) / 256, 256>>>(q, n4);
    convert_split_k_kernel<<<(n4 + 255) / 256, 256>>>(k, n4);
    transpose_v_kernel<<<dim3(BH_, S_ / 128), THREADS, 2 * 128 * TP_PAD * 2>>>(v);

    dim3 grid(BH_, S_ / TQ);
    sdpa_mma_kernel<<<grid, THREADS, SMEM_MAIN>>>(mask, out_ctx, out_attn);
}